// round 6
// baseline (speedup 1.0000x reference)
#include <cuda_runtime.h>

#define EPS_BN 1e-5f
#define EPS_RENORM 1e-9f

typedef unsigned long long ull;

// ---------------- problem constants ----------------
#define BATCH 8
#define CH    1024
#define NPTS  2048
#define CQK   128

// ---------------- scratch (no allocations allowed) ----------------
__device__ float g_x1 [BATCH * CH  * NPTS];                 // 64 MiB
__device__ float g_v  [BATCH * CH  * NPTS];                 // 64 MiB
__device__ float g_q  [BATCH * CQK * NPTS];                 // 8 MiB
__device__ float g_k  [BATCH * CQK * NPTS];                 // 8 MiB
__device__ float g_S  [(size_t)BATCH * NPTS * NPTS];        // 128 MiB
__device__ float g_t  [BATCH * CH  * NPTS];                 // 64 MiB
__device__ float g_rd [BATCH * NPTS];                       // reciprocal colsum

// ---------------- tiny PTX helpers ----------------
__device__ __forceinline__ ull pack2(float lo, float hi) {
    ull r;
    asm("mov.b64 %0, {%1, %2};" : "=l"(r)
        : "r"(__float_as_uint(lo)), "r"(__float_as_uint(hi)));
    return r;
}
__device__ __forceinline__ void unpack2(ull v, float& lo, float& hi) {
    unsigned a, b;
    asm("mov.b64 {%0, %1}, %2;" : "=r"(a), "=r"(b) : "l"(v));
    lo = __uint_as_float(a); hi = __uint_as_float(b);
}
__device__ __forceinline__ void ffma2(ull& d, ull a, ull b) {
    asm("fma.rn.f32x2 %0, %1, %2, %0;" : "+l"(d) : "l"(a), "l"(b));
}
__device__ __forceinline__ void cp16(void* smem_dst, const void* gmem_src) {
    unsigned d = (unsigned)__cvta_generic_to_shared(smem_dst);
    asm volatile("cp.async.cg.shared.global [%0], [%1], 16;"
                 :: "r"(d), "l"(gmem_src) : "memory");
}
__device__ __forceinline__ void cp_commit() {
    asm volatile("cp.async.commit_group;" ::: "memory");
}
#define CP_WAIT(n) asm volatile("cp.async.wait_group %0;" :: "n"(n) : "memory")

// ---------------- GEMM ----------------
// C[b] (M x N) = A[b] * B[b],  B stored [K][N] row-major (ldb = N).
// A_KM == false: A stored [M][K] row-major (lda = K)   (weights, V)
// A_KM == true : A stored [K][M] row-major (lda = M)   (Q for Q^T K)
enum { EPI_NONE = 0, EPI_BN_RELU = 1, EPI_SUB_DIV = 2, EPI_BN_RELU_ADD = 3 };

#define BM 128
#define BN 128
#define BK 16
#define TM 8
#define TN 8
#define PAD 4

template<bool A_KM, int EPI>
__global__ void __launch_bounds__(256)
gemm_kernel(const float* __restrict__ A, size_t sA,
            const float* __restrict__ B, size_t sB,
            float* __restrict__ C, size_t sC,
            int M, int N, int K,
            const float* __restrict__ gg, const float* __restrict__ bb,
            const float* __restrict__ mm, const float* __restrict__ vv,
            const float* __restrict__ add, size_t sAdd,
            const float* __restrict__ rdiv)
{
    // A buffer: A_KM -> [BK][BM+PAD] (16*132=2112), else [BM][BK+PAD] (128*20=2560)
    __shared__ float Ash[2][2560];
    __shared__ float Bsh[2][BK * BN];

    const int bz = blockIdx.z;
    const float* Ab = A + (size_t)bz * sA;
    const float* Bb = B + (size_t)bz * sB;
    float*       Cb = C + (size_t)bz * sC;

    const int rowStart = blockIdx.y * BM;
    const int colStart = blockIdx.x * BN;
    const int t  = threadIdx.x;
    const int tx = t & 15;          // 16 thread-cols
    const int ty = t >> 4;          // 16 thread-rows
    const int lda = A_KM ? M : K;
    const int ldb = N;

    ull acc[TM][TN / 2];
#pragma unroll
    for (int i = 0; i < TM; i++)
#pragma unroll
        for (int j = 0; j < TN / 2; j++) acc[i][j] = 0ULL;

    auto do_prefetch = [&](int k0, int s) {
        if (A_KM) {
#pragma unroll
            for (int p = 0; p < 2; p++) {
                int kr = (t >> 5) + p * 8;
                int m4 = (t & 31) * 4;
                cp16(&Ash[s][kr * (BM + PAD) + m4],
                     Ab + (size_t)(k0 + kr) * lda + rowStart + m4);
            }
        } else {
#pragma unroll
            for (int p = 0; p < 2; p++) {
                int r  = (t >> 2) + p * 64;
                int k4 = (t & 3) * 4;
                cp16(&Ash[s][r * (BK + PAD) + k4],
                     Ab + (size_t)(rowStart + r) * lda + k0 + k4);
            }
        }
#pragma unroll
        for (int p = 0; p < 2; p++) {
            int kr = (t >> 5) + p * 8;
            int n4 = (t & 31) * 4;
            cp16(&Bsh[s][kr * BN + n4],
                 Bb + (size_t)(k0 + kr) * ldb + colStart + n4);
        }
        cp_commit();
    };

    const int T = K / BK;
    do_prefetch(0, 0);
    int cur = 0;

    for (int tile = 0; tile < T; tile++) {
        if (tile + 1 < T) {
            do_prefetch((tile + 1) * BK, cur ^ 1);
            CP_WAIT(1);
        } else {
            CP_WAIT(0);
        }
        __syncthreads();

#pragma unroll
        for (int kk = 0; kk < BK; kk++) {
            ull rb[4];
            const ull* bp = (const ull*)&Bsh[cur][kk * BN + tx * TN];
            rb[0] = bp[0]; rb[1] = bp[1]; rb[2] = bp[2]; rb[3] = bp[3];
#pragma unroll
            for (int i = 0; i < TM; i++) {
                float a = A_KM
                    ? Ash[cur][kk * (BM + PAD) + ty * TM + i]
                    : Ash[cur][(ty * TM + i) * (BK + PAD) + kk];
                ull a2 = pack2(a, a);
                ffma2(acc[i][0], a2, rb[0]);
                ffma2(acc[i][1], a2, rb[1]);
                ffma2(acc[i][2], a2, rb[2]);
                ffma2(acc[i][3], a2, rb[3]);
            }
        }
        __syncthreads();
        cur ^= 1;
    }

    // epilogue
#pragma unroll
    for (int i = 0; i < TM; i++) {
        int r = rowStart + ty * TM + i;
        float s = 1.f, o = 0.f;
        if (EPI == EPI_BN_RELU || EPI == EPI_BN_RELU_ADD) {
            float inv = rsqrtf(vv[r] + EPS_BN);
            s = gg[r] * inv;
            o = bb[r] - mm[r] * s;
        }
        size_t base = (size_t)r * N + colStart + tx * TN;
        const float* addb = (EPI == EPI_SUB_DIV || EPI == EPI_BN_RELU_ADD)
                            ? add + (size_t)bz * sAdd : nullptr;
#pragma unroll
        for (int j = 0; j < TN / 2; j++) {
            float lo, hi; unpack2(acc[i][j], lo, hi);
            size_t idx = base + 2 * j;
            if (EPI == EPI_NONE) {
                Cb[idx]     = lo;
                Cb[idx + 1] = hi;
            } else if (EPI == EPI_BN_RELU) {
                Cb[idx]     = fmaxf(lo * s + o, 0.f);
                Cb[idx + 1] = fmaxf(hi * s + o, 0.f);
            } else if (EPI == EPI_SUB_DIV) {
                int c0 = colStart + tx * TN + 2 * j;
                float d0 = rdiv[(size_t)bz * N + c0];
                float d1 = rdiv[(size_t)bz * N + c0 + 1];
                Cb[idx]     = addb[idx]     - lo * d0;
                Cb[idx + 1] = addb[idx + 1] - hi * d1;
            } else { // EPI_BN_RELU_ADD
                Cb[idx]     = addb[idx]     + fmaxf(lo * s + o, 0.f);
                Cb[idx + 1] = addb[idx + 1] + fmaxf(hi * s + o, 0.f);
            }
        }
    }
}

// ---------------- row softmax (in place), one block per row ----------------
__global__ void __launch_bounds__(256)
softmax_kernel(float* __restrict__ S, int N)
{
    __shared__ float buf[NPTS];
    __shared__ float red[8];
    float* p = S + (size_t)blockIdx.x * N;
    int t = threadIdx.x;

    float mx = -3.402823466e38f;
    for (int i = t; i < N; i += 256) { float v = p[i]; buf[i] = v; mx = fmaxf(mx, v); }
#pragma unroll
    for (int o = 16; o > 0; o >>= 1) mx = fmaxf(mx, __shfl_xor_sync(0xffffffffu, mx, o));
    if ((t & 31) == 0) red[t >> 5] = mx;
    __syncthreads();
    float bm = red[0];
#pragma unroll
    for (int i = 1; i < 8; i++) bm = fmaxf(bm, red[i]);
    __syncthreads();

    float sum = 0.f;
    for (int i = t; i < N; i += 256) { float e = __expf(buf[i] - bm); buf[i] = e; sum += e; }
#pragma unroll
    for (int o = 16; o > 0; o >>= 1) sum += __shfl_xor_sync(0xffffffffu, sum, o);
    if ((t & 31) == 0) red[t >> 5] = sum;
    __syncthreads();
    float bs = 0.f;
#pragma unroll
    for (int i = 0; i < 8; i++) bs += red[i];
    float inv = 1.0f / bs;
    for (int i = t; i < N; i += 256) p[i] = buf[i] * inv;
}

// ---------------- column sums -> reciprocal of (eps + colsum) ----------------
__global__ void __launch_bounds__(256)
colsum_kernel(const float* __restrict__ S, float* __restrict__ rdiv, int N)
{
    int idx = blockIdx.x * 256 + threadIdx.x;   // 0 .. BATCH*N
    int b = idx / N, m = idx - b * N;
    const float* p = S + (size_t)b * N * N + m;
    float s[8] = {0.f, 0.f, 0.f, 0.f, 0.f, 0.f, 0.f, 0.f};
    for (int n = 0; n < N; n += 8) {
#pragma unroll
        for (int u = 0; u < 8; u++) s[u] += p[(size_t)(n + u) * N];
    }
    float tot = ((s[0] + s[1]) + (s[2] + s[3])) + ((s[4] + s[5]) + (s[6] + s[7]));
    rdiv[idx] = 1.0f / (EPS_RENORM + tot);
}

// ---------------- launch ----------------
extern "C" void kernel_launch(void* const* d_in, const int* in_sizes, int n_in,
                              void* d_out, int out_size)
{
    (void)in_sizes; (void)n_in; (void)out_size;
    const float* x  = (const float*)d_in[0];
    const float *W1 = (const float*)d_in[1],  *g1 = (const float*)d_in[2],
                *b1 = (const float*)d_in[3],  *m1 = (const float*)d_in[4],
                *v1 = (const float*)d_in[5];
    const float *W2 = (const float*)d_in[6],  *g2 = (const float*)d_in[7],
                *b2 = (const float*)d_in[8],  *m2 = (const float*)d_in[9],
                *v2 = (const float*)d_in[10];
    const float *W3 = (const float*)d_in[11], *g3 = (const float*)d_in[12],
                *b3 = (const float*)d_in[13], *m3 = (const float*)d_in[14],
                *v3 = (const float*)d_in[15];
    const float *W4 = (const float*)d_in[16], *g4 = (const float*)d_in[17],
                *b4 = (const float*)d_in[18], *m4 = (const float*)d_in[19],
                *v4 = (const float*)d_in[20];
    const float *W5 = (const float*)d_in[21], *g5 = (const float*)d_in[22],
                *b5 = (const float*)d_in[23], *m5 = (const float*)d_in[24],
                *v5 = (const float*)d_in[25];
    float* out = (float*)d_out;

    float *x1, *vb, *qb, *kb, *Sb, *tb, *rd;
    cudaGetSymbolAddress((void**)&x1, g_x1);
    cudaGetSymbolAddress((void**)&vb, g_v);
    cudaGetSymbolAddress((void**)&qb, g_q);
    cudaGetSymbolAddress((void**)&kb, g_k);
    cudaGetSymbolAddress((void**)&Sb, g_S);
    cudaGetSymbolAddress((void**)&tb, g_t);
    cudaGetSymbolAddress((void**)&rd, g_rd);

    const size_t sX  = (size_t)CH  * NPTS;
    const size_t sQK = (size_t)CQK * NPTS;
    const size_t sS  = (size_t)NPTS * NPTS;
    dim3 thr(256);

    // 1) x1 = relu(bn1(W1 @ x))
    gemm_kernel<false, EPI_BN_RELU><<<dim3(NPTS/BN, CH/BM, BATCH), thr>>>(
        W1, 0, x, sX, x1, sX, CH, NPTS, CH, g1, b1, m1, v1, nullptr, 0, nullptr);
    // 2) v = relu(bn2(W2 @ x1))
    gemm_kernel<false, EPI_BN_RELU><<<dim3(NPTS/BN, CH/BM, BATCH), thr>>>(
        W2, 0, x1, sX, vb, sX, CH, NPTS, CH, g2, b2, m2, v2, nullptr, 0, nullptr);
    // 3) q, 4) k
    gemm_kernel<false, EPI_BN_RELU><<<dim3(NPTS/BN, CQK/BM, BATCH), thr>>>(
        W3, 0, x1, sX, qb, sQK, CQK, NPTS, CH, g3, b3, m3, v3, nullptr, 0, nullptr);
    gemm_kernel<false, EPI_BN_RELU><<<dim3(NPTS/BN, CQK/BM, BATCH), thr>>>(
        W4, 0, x1, sX, kb, sQK, CQK, NPTS, CH, g4, b4, m4, v4, nullptr, 0, nullptr);
    // 5) scores = q^T k   (A stored [K=128][M=2048])
    gemm_kernel<true, EPI_NONE><<<dim3(NPTS/BN, NPTS/BM, BATCH), thr>>>(
        qb, sQK, kb, sQK, Sb, sS, NPTS, NPTS, CQK,
        nullptr, nullptr, nullptr, nullptr, nullptr, 0, nullptr);
    // 6) row softmax in place
    softmax_kernel<<<BATCH * NPTS, 256>>>(Sb, NPTS);
    // 7) reciprocal column-sum (renorm divisor)
    colsum_kernel<<<BATCH * NPTS / 256, 256>>>(Sb, rd, NPTS);
    // 8) t = x1 - (v @ S) * rdiv[col]
    gemm_kernel<false, EPI_SUB_DIV><<<dim3(NPTS/BN, CH/BM, BATCH), thr>>>(
        vb, sX, Sb, sS, tb, sX, CH, NPTS, NPTS,
        nullptr, nullptr, nullptr, nullptr, x1, sX, rd);
    // 9) out = x1 + relu(bn5(W5 @ t))
    gemm_kernel<false, EPI_BN_RELU_ADD><<<dim3(NPTS/BN, CH/BM, BATCH), thr>>>(
        W5, 0, tb, sX, out, sX, CH, NPTS, CH, g5, b5, m5, v5, x1, sX, nullptr);
}

// round 8
// speedup vs baseline: 2.3265x; 2.3265x over previous
#include <cuda_runtime.h>
#include <cuda_bf16.h>
#include <cstdint>

#define EPS_BN 1e-5f
#define EPS_RENORM 1e-9f

#define BATCH 8
#define CH    1024
#define NPTS  2048
#define CQK   128

typedef __nv_bfloat16 bf16;

// ---------------- scratch (no allocations allowed) ----------------
__device__ float g_x1[BATCH * CH * NPTS];                       // fp32 x1 (residual)
__device__ float g_S [(size_t)BATCH * NPTS * NPTS];             // fp32 scores
__device__ float g_rd[BATCH * NPTS];                            // 1/(eps+colsum)
__device__ bf16 g_xh [BATCH * CH * NPTS], g_xl [BATCH * CH * NPTS];
__device__ bf16 g_x1h[BATCH * CH * NPTS], g_x1l[BATCH * CH * NPTS];
__device__ bf16 g_vh [BATCH * CH * NPTS], g_vl [BATCH * CH * NPTS];
__device__ bf16 g_th [BATCH * CH * NPTS], g_tl [BATCH * CH * NPTS];
__device__ bf16 g_qh [BATCH * NPTS * CQK], g_ql[BATCH * NPTS * CQK];   // q^T [n][c]
__device__ bf16 g_kh [BATCH * CQK * NPTS], g_kl[BATCH * CQK * NPTS];
__device__ bf16 g_Sh [(size_t)BATCH * NPTS * NPTS], g_Sl[(size_t)BATCH * NPTS * NPTS];
__device__ bf16 g_W1h[CH * CH],  g_W1l[CH * CH];
__device__ bf16 g_W2h[CH * CH],  g_W2l[CH * CH];
__device__ bf16 g_W5h[CH * CH],  g_W5l[CH * CH];
__device__ bf16 g_W3h[CQK * CH], g_W3l[CQK * CH];
__device__ bf16 g_W4h[CQK * CH], g_W4l[CQK * CH];

// ---------------- PTX helpers ----------------
__device__ __forceinline__ uint32_t s2u(const void* p) {
    uint32_t a;
    asm("{ .reg .u64 t; cvta.to.shared.u64 t, %1; cvt.u32.u64 %0, t; }"
        : "=r"(a) : "l"(p));
    return a;
}
__device__ __forceinline__ void cp16(uint32_t saddr, const void* g) {
    asm volatile("cp.async.cg.shared.global [%0], [%1], 16;"
                 :: "r"(saddr), "l"(g) : "memory");
}
#define CP_COMMIT() asm volatile("cp.async.commit_group;" ::: "memory")
#define CP_WAIT(n)  asm volatile("cp.async.wait_group %0;" :: "n"(n) : "memory")

__device__ __forceinline__ void ldsm4(uint32_t* r, uint32_t a) {
    asm volatile("ldmatrix.sync.aligned.m8n8.x4.shared.b16 {%0,%1,%2,%3}, [%4];"
                 : "=r"(r[0]), "=r"(r[1]), "=r"(r[2]), "=r"(r[3]) : "r"(a));
}
__device__ __forceinline__ void ldsm4t(uint32_t* r, uint32_t a) {
    asm volatile("ldmatrix.sync.aligned.m8n8.x4.trans.shared.b16 {%0,%1,%2,%3}, [%4];"
                 : "=r"(r[0]), "=r"(r[1]), "=r"(r[2]), "=r"(r[3]) : "r"(a));
}
__device__ __forceinline__ void mma16816(float* d, const uint32_t* a, const uint32_t* b) {
    asm volatile("mma.sync.aligned.m16n8k16.row.col.f32.bf16.bf16.f32 "
                 "{%0,%1,%2,%3}, {%4,%5,%6,%7}, {%8,%9}, {%0,%1,%2,%3};"
                 : "+f"(d[0]), "+f"(d[1]), "+f"(d[2]), "+f"(d[3])
                 : "r"(a[0]), "r"(a[1]), "r"(a[2]), "r"(a[3]), "r"(b[0]), "r"(b[1]));
}

// ---------------- split-bf16 MMA GEMM ----------------
// C[b] (M x N) = (Ah+Al)[b] @ (Bh+Bl)[b] ; 3-term split product.
// A row-major [M][K], B row-major [K][N], N == NPTS always.
// CTA 128x128, BK=32, 8 warps (warp tile 32x64), 4-stage cp.async pipeline.
#define NSTG   4
#define STG_B  32768
#define SMEM_GEMM (NSTG * STG_B)      // 128 KiB dynamic

enum { EP_X1 = 0, EP_BNR = 1, EP_BNR_T = 2, EP_S = 3, EP_SUBDIV = 4, EP_FINAL = 5 };

template<int EPI, bool ABATCH>
__global__ void __launch_bounds__(256)
mma_gemm(const bf16* __restrict__ Ahp, const bf16* __restrict__ Alp, size_t sA,
         const bf16* __restrict__ Bhp, const bf16* __restrict__ Blp, size_t sB,
         int M, int K,
         float* __restrict__ C32, bf16* __restrict__ Ch, bf16* __restrict__ Cl,
         const float* __restrict__ gg, const float* __restrict__ bb,
         const float* __restrict__ mm, const float* __restrict__ vv,
         const float* __restrict__ add, const float* __restrict__ rdiv)
{
    extern __shared__ __align__(256) char smraw[];
    const uint32_t smb = s2u(smraw);
    const int tid  = threadIdx.x;
    const int lane = tid & 31;
    const int wid  = tid >> 5;
    const int m_w  = (wid & 3) * 32;     // warp M offset
    const int n_w  = (wid >> 2) * 64;    // warp N offset
    const int bz   = blockIdx.z;
    const int rowStart = blockIdx.y * 128;
    const int colStart = blockIdx.x * 128;
    const int N = NPTS;

    const bf16* Ah_ = Ahp + (ABATCH ? (size_t)bz * sA : 0);
    const bf16* Al_ = Alp + (ABATCH ? (size_t)bz * sA : 0);
    const bf16* Bh_ = Bhp + (size_t)bz * sB;
    const bf16* Bl_ = Blp + (size_t)bz * sB;

    float acc[2][8][4];
#pragma unroll
    for (int i = 0; i < 2; i++)
#pragma unroll
        for (int j = 0; j < 8; j++)
#pragma unroll
            for (int r = 0; r < 4; r++) acc[i][j][r] = 0.f;

    // stage layout: Ah @0 (8K) | Al @8192 | Bh @16384 | Bl @24576
    auto loadStage = [&](int t) {
        const int s = t & (NSTG - 1);
        const uint32_t base = smb + (uint32_t)s * STG_B;
        const int k0 = t * 32;
#pragma unroll
        for (int i = 0; i < 2; i++) {            // A: 128 rows x 4 chunks (16B)
            int idx = tid + i * 256;
            int row = idx >> 2, c = idx & 3;
            uint32_t off = (uint32_t)(row * 64 + ((c ^ ((row >> 1) & 3)) << 4));
            size_t go = (size_t)(rowStart + row) * K + k0 + c * 8;
            cp16(base + off,        Ah_ + go);
            cp16(base + 8192 + off, Al_ + go);
        }
#pragma unroll
        for (int i = 0; i < 2; i++) {            // B: 32 rows x 16 chunks
            int idx = tid + i * 256;
            int k = idx >> 4, cn = idx & 15;
            uint32_t off = (uint32_t)(k * 256 + ((cn ^ (k & 7)) << 4));
            size_t go = (size_t)(k0 + k) * N + colStart + cn * 8;
            cp16(base + 16384 + off, Bh_ + go);
            cp16(base + 24576 + off, Bl_ + go);
        }
        CP_COMMIT();
    };

    const int T = K / 32;
    const int P = (T < 3) ? T : 3;
    for (int t = 0; t < P; t++) loadStage(t);

    for (int t = 0; t < T; t++) {
        const int rem = T - t;
        if (rem >= 3) { CP_WAIT(2); } else if (rem == 2) { CP_WAIT(1); } else { CP_WAIT(0); }
        __syncthreads();
        if (t + 3 < T) loadStage(t + 3);

        const uint32_t Ab = smb + (uint32_t)(t & (NSTG - 1)) * STG_B;
#pragma unroll
        for (int ks = 0; ks < 2; ks++) {
            uint32_t ah[2][4], al[2][4];
#pragma unroll
            for (int i = 0; i < 2; i++) {
                int row = m_w + i * 16 + (lane & 15);
                int c = ks * 2 + (lane >> 4);
                uint32_t off = (uint32_t)(row * 64 + ((c ^ ((row >> 1) & 3)) << 4));
                ldsm4(ah[i], Ab + off);
                ldsm4(al[i], Ab + 8192 + off);
            }
            uint32_t bh[8][2], bl[8][2];
#pragma unroll
            for (int p = 0; p < 4; p++) {
                int g = lane >> 3, j = lane & 7;
                int k = ks * 16 + (g & 1) * 8 + j;
                int cn = (n_w >> 3) + p * 2 + (g >> 1);
                uint32_t off = (uint32_t)(k * 256 + ((cn ^ (k & 7)) << 4));
                uint32_t r4[4];
                ldsm4t(r4, Ab + 16384 + off);
                bh[2 * p][0] = r4[0]; bh[2 * p][1] = r4[1];
                bh[2 * p + 1][0] = r4[2]; bh[2 * p + 1][1] = r4[3];
                ldsm4t(r4, Ab + 24576 + off);
                bl[2 * p][0] = r4[0]; bl[2 * p][1] = r4[1];
                bl[2 * p + 1][0] = r4[2]; bl[2 * p + 1][1] = r4[3];
            }
#pragma unroll
            for (int i = 0; i < 2; i++)
#pragma unroll
                for (int j = 0; j < 8; j++) {
                    mma16816(acc[i][j], ah[i], bh[j]);
                    mma16816(acc[i][j], ah[i], bl[j]);
                    mma16816(acc[i][j], al[i], bh[j]);
                }
        }
    }

    // ---------------- epilogue ----------------
    __shared__ float s_scl[128], s_off[128];
    if (EPI == EP_X1 || EPI == EP_BNR || EPI == EP_BNR_T || EPI == EP_FINAL) {
        if (tid < 128) {
            int rg = rowStart + tid;
            float inv = rsqrtf(vv[rg] + EPS_BN);
            float sc = gg[rg] * inv;
            s_scl[tid] = sc;
            s_off[tid] = bb[rg] - mm[rg] * sc;
        }
        __syncthreads();
    }

    const size_t sC = (size_t)M * N;
#pragma unroll
    for (int i = 0; i < 2; i++) {
#pragma unroll
        for (int j = 0; j < 8; j++) {
#pragma unroll
            for (int hseg = 0; hseg < 2; hseg++) {
                const int rl = m_w + i * 16 + (lane >> 2) + hseg * 8;
                const int cl = n_w + j * 8 + (lane & 3) * 2;
                const float y0 = acc[i][j][hseg * 2];
                const float y1 = acc[i][j][hseg * 2 + 1];
                const int rg = rowStart + rl;
                const int cg = colStart + cl;
                const size_t o = (size_t)bz * sC + (size_t)rg * N + cg;

                if (EPI == EP_S) {
                    float2 v2; v2.x = y0; v2.y = y1;
                    *(float2*)(C32 + o) = v2;
                } else if (EPI == EP_SUBDIV) {
                    float2 ad  = *(const float2*)(add + o);
                    float2 rdv = *(const float2*)(rdiv + (size_t)bz * N + cg);
                    float z0 = ad.x - y0 * rdv.x;
                    float z1 = ad.y - y1 * rdv.y;
                    bf16 h0 = __float2bfloat16(z0), h1 = __float2bfloat16(z1);
                    __nv_bfloat162 hh; hh.x = h0; hh.y = h1;
                    __nv_bfloat162 ll;
                    ll.x = __float2bfloat16(z0 - __bfloat162float(h0));
                    ll.y = __float2bfloat16(z1 - __bfloat162float(h1));
                    *(__nv_bfloat162*)(Ch + o) = hh;
                    *(__nv_bfloat162*)(Cl + o) = ll;
                } else {
                    const float sc = s_scl[rl], of = s_off[rl];
                    float z0 = fmaxf(y0 * sc + of, 0.f);
                    float z1 = fmaxf(y1 * sc + of, 0.f);
                    if (EPI == EP_BNR_T) {
                        // q^T: out[(point)][channel], point = cg, channel = rg
                        size_t ot = (size_t)bz * ((size_t)NPTS * CQK);
                        size_t o0 = ot + (size_t)cg * CQK + rg;
                        size_t o1 = o0 + CQK;
                        bf16 h0 = __float2bfloat16(z0), h1 = __float2bfloat16(z1);
                        Ch[o0] = h0; Cl[o0] = __float2bfloat16(z0 - __bfloat162float(h0));
                        Ch[o1] = h1; Cl[o1] = __float2bfloat16(z1 - __bfloat162float(h1));
                    } else if (EPI == EP_FINAL) {
                        float2 ad = *(const float2*)(add + o);
                        float2 v2; v2.x = ad.x + z0; v2.y = ad.y + z1;
                        *(float2*)(C32 + o) = v2;
                    } else {
                        if (EPI == EP_X1) {
                            float2 v2; v2.x = z0; v2.y = z1;
                            *(float2*)(C32 + o) = v2;
                        }
                        bf16 h0 = __float2bfloat16(z0), h1 = __float2bfloat16(z1);
                        __nv_bfloat162 hh; hh.x = h0; hh.y = h1;
                        __nv_bfloat162 ll;
                        ll.x = __float2bfloat16(z0 - __bfloat162float(h0));
                        ll.y = __float2bfloat16(z1 - __bfloat162float(h1));
                        *(__nv_bfloat162*)(Ch + o) = hh;
                        *(__nv_bfloat162*)(Cl + o) = ll;
                    }
                }
            }
        }
    }
}

// ---------------- fp32 -> bf16 hi/lo split ----------------
__global__ void __launch_bounds__(256)
split_kernel(const float* __restrict__ in, bf16* __restrict__ hi, bf16* __restrict__ lo)
{
    size_t i = (size_t)blockIdx.x * 256 + threadIdx.x;
    float v = in[i];
    bf16 h = __float2bfloat16(v);
    hi[i] = h;
    lo[i] = __float2bfloat16(v - __bfloat162float(h));
}

// ---------------- row softmax: fp32 in, bf16 hi/lo out ----------------
__global__ void __launch_bounds__(256)
softmax_kernel(const float* __restrict__ S, bf16* __restrict__ Sh, bf16* __restrict__ Sl)
{
    __shared__ float buf[NPTS];
    __shared__ float red[8];
    const float* p = S + (size_t)blockIdx.x * NPTS;
    bf16* ph = Sh + (size_t)blockIdx.x * NPTS;
    bf16* pl = Sl + (size_t)blockIdx.x * NPTS;
    int t = threadIdx.x;

    float mx = -3.402823466e38f;
    for (int i = t; i < NPTS; i += 256) { float v = p[i]; buf[i] = v; mx = fmaxf(mx, v); }
#pragma unroll
    for (int o = 16; o > 0; o >>= 1) mx = fmaxf(mx, __shfl_xor_sync(0xffffffffu, mx, o));
    if ((t & 31) == 0) red[t >> 5] = mx;
    __syncthreads();
    float bm = red[0];
#pragma unroll
    for (int i = 1; i < 8; i++) bm = fmaxf(bm, red[i]);
    __syncthreads();

    float sum = 0.f;
    for (int i = t; i < NPTS; i += 256) { float e = __expf(buf[i] - bm); buf[i] = e; sum += e; }
#pragma unroll
    for (int o = 16; o > 0; o >>= 1) sum += __shfl_xor_sync(0xffffffffu, sum, o);
    if ((t & 31) == 0) red[t >> 5] = sum;
    __syncthreads();
    float bs = 0.f;
#pragma unroll
    for (int i = 0; i < 8; i++) bs += red[i];
    float inv = 1.0f / bs;
    for (int i = t; i < NPTS; i += 256) {
        float v = buf[i] * inv;
        bf16 h = __float2bfloat16(v);
        ph[i] = h;
        pl[i] = __float2bfloat16(v - __bfloat162float(h));
    }
}

// ---------------- column sums -> 1/(eps+colsum) ----------------
__global__ void __launch_bounds__(256)
colsum_kernel(const bf16* __restrict__ Sh, const bf16* __restrict__ Sl,
              float* __restrict__ rdiv)
{
    int idx = blockIdx.x * 256 + threadIdx.x;
    int b = idx / NPTS, m = idx - b * NPTS;
    const bf16* ph = Sh + (size_t)b * NPTS * NPTS + m;
    const bf16* pl = Sl + (size_t)b * NPTS * NPTS + m;
    float s[4] = {0.f, 0.f, 0.f, 0.f};
    for (int n = 0; n < NPTS; n += 4) {
#pragma unroll
        for (int u = 0; u < 4; u++) {
            size_t o = (size_t)(n + u) * NPTS;
            s[u] += __bfloat162float(ph[o]) + __bfloat162float(pl[o]);
        }
    }
    rdiv[idx] = 1.0f / (EPS_RENORM + ((s[0] + s[1]) + (s[2] + s[3])));
}

// ---------------- launch ----------------
extern "C" void kernel_launch(void* const* d_in, const int* in_sizes, int n_in,
                              void* d_out, int out_size)
{
    (void)in_sizes; (void)n_in; (void)out_size;
    const float* x  = (const float*)d_in[0];
    const float *W1 = (const float*)d_in[1],  *g1 = (const float*)d_in[2],
                *b1 = (const float*)d_in[3],  *m1 = (const float*)d_in[4],
                *v1 = (const float*)d_in[5];
    const float *W2 = (const float*)d_in[6],  *g2 = (const float*)d_in[7],
                *b2 = (const float*)d_in[8],  *m2 = (const float*)d_in[9],
                *v2 = (const float*)d_in[10];
    const float *W3 = (const float*)d_in[11], *g3 = (const float*)d_in[12],
                *b3 = (const float*)d_in[13], *m3 = (const float*)d_in[14],
                *v3 = (const float*)d_in[15];
    const float *W4 = (const float*)d_in[16], *g4 = (const float*)d_in[17],
                *b4 = (const float*)d_in[18], *m4 = (const float*)d_in[19],
                *v4 = (const float*)d_in[20];
    const float *W5 = (const float*)d_in[21], *g5 = (const float*)d_in[22],
                *b5 = (const float*)d_in[23], *m5 = (const float*)d_in[24],
                *v5 = (const float*)d_in[25];
    float* out = (float*)d_out;

    float *x1, *S, *rd;
    bf16 *xh, *xl, *x1h, *x1l, *vh, *vl, *th, *tl, *qh, *ql, *kh, *kl, *Sh, *Sl;
    bf16 *W1h, *W1l, *W2h, *W2l, *W3h, *W3l, *W4h, *W4l, *W5h, *W5l;
    cudaGetSymbolAddress((void**)&x1, g_x1);
    cudaGetSymbolAddress((void**)&S,  g_S);
    cudaGetSymbolAddress((void**)&rd, g_rd);
    cudaGetSymbolAddress((void**)&xh, g_xh);   cudaGetSymbolAddress((void**)&xl, g_xl);
    cudaGetSymbolAddress((void**)&x1h, g_x1h); cudaGetSymbolAddress((void**)&x1l, g_x1l);
    cudaGetSymbolAddress((void**)&vh, g_vh);   cudaGetSymbolAddress((void**)&vl, g_vl);
    cudaGetSymbolAddress((void**)&th, g_th);   cudaGetSymbolAddress((void**)&tl, g_tl);
    cudaGetSymbolAddress((void**)&qh, g_qh);   cudaGetSymbolAddress((void**)&ql, g_ql);
    cudaGetSymbolAddress((void**)&kh, g_kh);   cudaGetSymbolAddress((void**)&kl, g_kl);
    cudaGetSymbolAddress((void**)&Sh, g_Sh);   cudaGetSymbolAddress((void**)&Sl, g_Sl);
    cudaGetSymbolAddress((void**)&W1h, g_W1h); cudaGetSymbolAddress((void**)&W1l, g_W1l);
    cudaGetSymbolAddress((void**)&W2h, g_W2h); cudaGetSymbolAddress((void**)&W2l, g_W2l);
    cudaGetSymbolAddress((void**)&W3h, g_W3h); cudaGetSymbolAddress((void**)&W3l, g_W3l);
    cudaGetSymbolAddress((void**)&W4h, g_W4h); cudaGetSymbolAddress((void**)&W4l, g_W4l);
    cudaGetSymbolAddress((void**)&W5h, g_W5h); cudaGetSymbolAddress((void**)&W5l, g_W5l);

    cudaFuncSetAttribute(mma_gemm<EP_X1, false>,    cudaFuncAttributeMaxDynamicSharedMemorySize, SMEM_GEMM);
    cudaFuncSetAttribute(mma_gemm<EP_BNR, false>,   cudaFuncAttributeMaxDynamicSharedMemorySize, SMEM_GEMM);
    cudaFuncSetAttribute(mma_gemm<EP_BNR_T, false>, cudaFuncAttributeMaxDynamicSharedMemorySize, SMEM_GEMM);
    cudaFuncSetAttribute(mma_gemm<EP_S, true>,      cudaFuncAttributeMaxDynamicSharedMemorySize, SMEM_GEMM);
    cudaFuncSetAttribute(mma_gemm<EP_SUBDIV, true>, cudaFuncAttributeMaxDynamicSharedMemorySize, SMEM_GEMM);
    cudaFuncSetAttribute(mma_gemm<EP_FINAL, false>, cudaFuncAttributeMaxDynamicSharedMemorySize, SMEM_GEMM);

    const size_t sX  = (size_t)CH * NPTS;     // [1024][2048]
    const size_t sQT = (size_t)NPTS * CQK;    // q^T [2048][128]
    const size_t sK  = (size_t)CQK * NPTS;    // k [128][2048]
    const size_t sS  = (size_t)NPTS * NPTS;

    // splits of inputs
    split_kernel<<<(BATCH * CH * NPTS) / 256, 256>>>(x, xh, xl);
    split_kernel<<<(CH * CH) / 256, 256>>>(W1, W1h, W1l);
    split_kernel<<<(CH * CH) / 256, 256>>>(W2, W2h, W2l);
    split_kernel<<<(CQK * CH) / 256, 256>>>(W3, W3h, W3l);
    split_kernel<<<(CQK * CH) / 256, 256>>>(W4, W4h, W4l);
    split_kernel<<<(CH * CH) / 256, 256>>>(W5, W5h, W5l);

    // 1) x1 = relu(bn1(W1 @ x))  -> fp32 + bf16 hi/lo
    mma_gemm<EP_X1, false><<<dim3(16, 8, 8), 256, SMEM_GEMM>>>(
        W1h, W1l, 0, xh, xl, sX, CH, CH,
        x1, x1h, x1l, g1, b1, m1, v1, nullptr, nullptr);
    // 2) v = relu(bn2(W2 @ x1))
    mma_gemm<EP_BNR, false><<<dim3(16, 8, 8), 256, SMEM_GEMM>>>(
        W2h, W2l, 0, x1h, x1l, sX, CH, CH,
        nullptr, vh, vl, g2, b2, m2, v2, nullptr, nullptr);
    // 3) q (stored transposed q^T [n][c])
    mma_gemm<EP_BNR_T, false><<<dim3(16, 1, 8), 256, SMEM_GEMM>>>(
        W3h, W3l, 0, x1h, x1l, sX, CQK, CH,
        nullptr, qh, ql, g3, b3, m3, v3, nullptr, nullptr);
    // 4) k
    mma_gemm<EP_BNR, false><<<dim3(16, 1, 8), 256, SMEM_GEMM>>>(
        W4h, W4l, 0, x1h, x1l, sX, CQK, CH,
        nullptr, kh, kl, g4, b4, m4, v4, nullptr, nullptr);
    // 5) scores S[n][m] = sum_c qT[n][c] k[c][m]  (fp32)
    mma_gemm<EP_S, true><<<dim3(16, 16, 8), 256, SMEM_GEMM>>>(
        qh, ql, sQT, kh, kl, sK, NPTS, CQK,
        S, nullptr, nullptr, nullptr, nullptr, nullptr, nullptr, nullptr, nullptr);
    // 6) row softmax -> bf16 hi/lo
    softmax_kernel<<<BATCH * NPTS, 256>>>(S, Sh, Sl);
    // 7) renorm divisor
    colsum_kernel<<<(BATCH * NPTS) / 256, 256>>>(Sh, Sl, rd);
    // 8) t = x1 - (v @ S) * rdiv[col]  -> bf16 hi/lo
    mma_gemm<EP_SUBDIV, true><<<dim3(16, 8, 8), 256, SMEM_GEMM>>>(
        vh, vl, sX, Sh, Sl, sS, CH, NPTS,
        nullptr, th, tl, nullptr, nullptr, nullptr, nullptr, x1, rd);
    // 9) out = x1 + relu(bn5(W5 @ t))
    mma_gemm<EP_FINAL, false><<<dim3(16, 8, 8), 256, SMEM_GEMM>>>(
        W5h, W5l, 0, th, tl, sX, CH, CH,
        out, nullptr, nullptr, g5, b5, m5, v5, x1, nullptr);
}